// round 10
// baseline (speedup 1.0000x reference)
#include <cuda_runtime.h>
#include <cstddef>

// 3D Haar wavelet (frames valid, h/w 'same' right-zero-pad), all 8 subbands fused.
// x: (2,3,16,256,256) f32. Out: LLL (2,3,15,256,256) then detail (2,3,105,256,256)
// detail order along axis2: LLH, LHL, LHH, HLL, HLH, HHL, HHH
//
// R9 = R8 body (h-pairing, scalar boundary loads, __stcs stores, 128-thr CTAs,
// 72 regs -> 7 CTAs/SM) made PERSISTENT: grid = 148*7 = 1036 CTAs, each thread
// grid-strides over ~5-6 strips. Removes the 5.56-wave quantization + ragged
// tail (DRAM% proved occupancy-insensitive at ~61%, so the remaining loss is
// scheduling, not bandwidth).

#define NBC   6        // 2*3
#define NF    15
#define NH    256
#define NW    256
#define NW4   64       // NW/4
#define NHP   128      // NH/2 output-row pairs
#define FRAME_STRIDE 65536   // 256*256
#define LLL_ELEMS 5898240    // 6*15*65536
#define TOTAL_STRIPS (NBC * NF * NHP * NW4)   // 737,280
#define S3 0.04419417382415922f  // 1/(16*sqrt(2))

#define GRID_CTAS 1036   // 148 SMs * 7 CTAs
#define BLOCK_THR 128

__global__ void __launch_bounds__(BLOCK_THR, 7) haar3d_kernel(
    const float* __restrict__ x,
    float* __restrict__ out_lll,
    float* __restrict__ out_det)
{
    const int stride = GRID_CTAS * BLOCK_THR;   // 132,608

    for (int idx = blockIdx.x * BLOCK_THR + threadIdx.x;
         idx < TOTAL_STRIPS; idx += stride)
    {
        int wv   = idx & (NW4 - 1);
        int hp   = (idx >> 6) & (NHP - 1);
        int rest = idx >> 13;          // bc*NF + f
        int f    = rest % NF;
        int bc   = rest / NF;
        int w0   = wv << 2;
        int h0   = hp << 1;            // first output row of the pair (0..254)

        const float* base = x + ((size_t)(bc * 16 + f)) * FRAME_STRIDE + h0 * NW + w0;
        const bool wtail = (wv == NW4 - 1);   // last strip: w0==252
        const bool hend  = (hp == NHP - 1);   // h0==254 -> row h0+2 is zero pad

        // raw rows: frame a = f, frame b = f+1; rows 0..2 = h0, h0+1, h0+2
        float a0[5], a1[5], a2[5], b0[5], b1[5], b2[5];

        #define LOAD_ROW(P, SRC) do {                                   \
            float4 _v = *(const float4*)(SRC);                          \
            P[0]=_v.x; P[1]=_v.y; P[2]=_v.z; P[3]=_v.w;                 \
            P[4] = wtail ? 0.f : (SRC)[4];                              \
        } while (0)

        LOAD_ROW(a0, base);
        LOAD_ROW(a1, base + NW);
        LOAD_ROW(b0, base + FRAME_STRIDE);
        LOAD_ROW(b1, base + FRAME_STRIDE + NW);
        if (!hend) {   // warp-uniform branch
            LOAD_ROW(a2, base + 2 * NW);
            LOAD_ROW(b2, base + FRAME_STRIDE + 2 * NW);
        } else {
            #pragma unroll
            for (int k = 0; k < 5; k++) { a2[k] = 0.f; b2[k] = 0.f; }
        }

        // output bases (row h0); row h0+1 = +NW
        size_t plane = (size_t)h0 * NW + w0;
        float* oL = out_lll + ((size_t)(bc * NF + f)) * FRAME_STRIDE + plane;
        float* oD = out_det + ((size_t)(bc * 7 * NF + f)) * FRAME_STRIDE + plane;

        // Compute + store all 8 subbands for one output row.
        #define DO_ROW(ALO, AHI, BLO, BHI, ROWOFF) do {                              \
            float4 vLLL, vLLH, vLHL, vLHH, vHLL, vHLH, vHHL, vHHH;                   \
            float* rLLL=&vLLL.x; float* rLLH=&vLLH.x; float* rLHL=&vLHL.x;           \
            float* rLHH=&vLHH.x; float* rHLL=&vHLL.x; float* rHLH=&vHLH.x;           \
            float* rHHL=&vHHL.x; float* rHHH=&vHHH.x;                                \
            _Pragma("unroll")                                                        \
            for (int k = 0; k < 4; k++) {                                            \
                float wl00 = ALO[k] + ALO[k+1], wh00 = ALO[k+1] - ALO[k];            \
                float wl01 = AHI[k] + AHI[k+1], wh01 = AHI[k+1] - AHI[k];            \
                float wl10 = BLO[k] + BLO[k+1], wh10 = BLO[k+1] - BLO[k];            \
                float wl11 = BHI[k] + BHI[k+1], wh11 = BHI[k+1] - BHI[k];            \
                float q0LL = wl00 + wl01, q0LH = wh00 + wh01;                        \
                float q0HL = wl01 - wl00, q0HH = wh01 - wh00;                        \
                float q1LL = wl10 + wl11, q1LH = wh10 + wh11;                        \
                float q1HL = wl11 - wl10, q1HH = wh11 - wh10;                        \
                rLLL[k] = S3 * (q0LL + q1LL);                                        \
                rLLH[k] = S3 * (q0LH + q1LH);                                        \
                rLHL[k] = S3 * (q0HL + q1HL);                                        \
                rLHH[k] = S3 * (q0HH + q1HH);                                        \
                rHLL[k] = S3 * (q1LL - q0LL);                                        \
                rHLH[k] = S3 * (q1LH - q0LH);                                        \
                rHHL[k] = S3 * (q1HL - q0HL);                                        \
                rHHH[k] = S3 * (q1HH - q0HH);                                        \
            }                                                                        \
            __stcs((float4*)(oL + (ROWOFF)), vLLL);                                  \
            __stcs((float4*)(oD + (size_t)0 * NF * FRAME_STRIDE + (ROWOFF)), vLLH);  \
            __stcs((float4*)(oD + (size_t)1 * NF * FRAME_STRIDE + (ROWOFF)), vLHL);  \
            __stcs((float4*)(oD + (size_t)2 * NF * FRAME_STRIDE + (ROWOFF)), vLHH);  \
            __stcs((float4*)(oD + (size_t)3 * NF * FRAME_STRIDE + (ROWOFF)), vHLL);  \
            __stcs((float4*)(oD + (size_t)4 * NF * FRAME_STRIDE + (ROWOFF)), vHLH);  \
            __stcs((float4*)(oD + (size_t)5 * NF * FRAME_STRIDE + (ROWOFF)), vHHL);  \
            __stcs((float4*)(oD + (size_t)6 * NF * FRAME_STRIDE + (ROWOFF)), vHHH);  \
        } while (0)

        DO_ROW(a0, a1, b0, b1, 0);     // output row h0   (input rows h0, h0+1)
        DO_ROW(a1, a2, b1, b2, NW);    // output row h0+1 (input rows h0+1, h0+2)

        #undef DO_ROW
        #undef LOAD_ROW
    }
}

extern "C" void kernel_launch(void* const* d_in, const int* in_sizes, int n_in,
                              void* d_out, int out_size)
{
    const float* x = (const float*)d_in[0];
    float* out = (float*)d_out;
    float* out_lll = out;
    float* out_det = out + LLL_ELEMS;

    haar3d_kernel<<<GRID_CTAS, BLOCK_THR>>>(x, out_lll, out_det);
}

// round 12
// speedup vs baseline: 1.0875x; 1.0875x over previous
#include <cuda_runtime.h>
#include <cstddef>

// 3D Haar wavelet (frames valid, h/w 'same' right-zero-pad), all 8 subbands fused.
// x: (2,3,16,256,256) f32. Out: LLL (2,3,15,256,256) then detail (2,3,105,256,256)
// detail order along axis2: LLH, LHL, LHH, HLL, HLH, HHL, HHH
//
// R10 = R5 + f-pairing: each thread produces output frames (f0, f0+1) x output
// rows (h0, h0+1) for one 4-wide strip, loading a 3x3 (frame x row) input block
// = 9 rows instead of 12 -> load instrs per output row 3 -> 2.25 (-25%), the
// lever that paid in R5. NF=15 odd: fp==7 computes only frame 14 (warp-uniform).
// Stores unchanged: 4-wide contiguous strips, 512B coalesced, __stcs.
// 128-thr CTAs + launch_bounds(128,5): reg cap 102 >= ~95 needed, no spills.
// (R9 persistent loop regressed: serialized iterations killed MLP; reverted.)

#define NBC   6        // 2*3
#define NF    15
#define NFP   8        // ceil(NF/2) output-frame pairs
#define NH    256
#define NW    256
#define NW4   64       // NW/4
#define NHP   128      // NH/2 output-row pairs
#define FRAME_STRIDE 65536   // 256*256
#define LLL_ELEMS 5898240    // 6*15*65536
#define S3 0.04419417382415922f  // 1/(16*sqrt(2))

__global__ void __launch_bounds__(128, 5) haar3d_kernel(
    const float* __restrict__ x,
    float* __restrict__ out_lll,
    float* __restrict__ out_det)
{
    int idx = blockIdx.x * blockDim.x + threadIdx.x;
    // total threads = NBC*NFP*NHP*NW4 = 6*8*128*64 = 393,216 (grid exact)
    int wv   = idx & (NW4 - 1);
    int hp   = (idx >> 6) & (NHP - 1);
    int rest = idx >> 13;          // bc*NFP + fp
    int fp   = rest & (NFP - 1);
    int bc   = rest >> 3;
    int w0   = wv << 2;
    int h0   = hp << 1;            // first output row of the pair (0..254)
    int f0   = fp << 1;            // first output frame of the pair (0..14)

    const float* base = x + ((size_t)(bc * 16 + f0)) * FRAME_STRIDE + h0 * NW + w0;
    const bool wtail = (wv == NW4 - 1);   // last strip: w0==252
    const bool hend  = (hp == NHP - 1);   // h0==254 -> row h0+2 is zero pad
    const bool flast = (fp == NFP - 1);   // f0==14 -> only one output frame

    // raw rows: frames a=f0, b=f0+1, c=f0+2 ; rows 0..2 = h0, h0+1, h0+2
    float a0[5], a1[5], a2[5], b0[5], b1[5], b2[5], c0[5], c1[5], c2[5];

    #define LOAD_ROW(P, SRC) do {                                   \
        float4 _v = *(const float4*)(SRC);                          \
        P[0]=_v.x; P[1]=_v.y; P[2]=_v.z; P[3]=_v.w;                 \
        P[4] = wtail ? 0.f : (SRC)[4];                              \
    } while (0)
    #define ZERO_ROW(P) do {                                        \
        _Pragma("unroll")                                           \
        for (int _k = 0; _k < 5; _k++) P[_k] = 0.f;                 \
    } while (0)

    LOAD_ROW(a0, base);
    LOAD_ROW(a1, base + NW);
    LOAD_ROW(b0, base + FRAME_STRIDE);
    LOAD_ROW(b1, base + FRAME_STRIDE + NW);
    if (!hend) {                       // warp-uniform
        LOAD_ROW(a2, base + 2 * NW);
        LOAD_ROW(b2, base + FRAME_STRIDE + 2 * NW);
    } else { ZERO_ROW(a2); ZERO_ROW(b2); }
    if (!flast) {                      // warp-uniform
        LOAD_ROW(c0, base + 2 * FRAME_STRIDE);
        LOAD_ROW(c1, base + 2 * FRAME_STRIDE + NW);
        if (!hend) LOAD_ROW(c2, base + 2 * FRAME_STRIDE + 2 * NW);
        else       ZERO_ROW(c2);
    } else { ZERO_ROW(c0); ZERO_ROW(c1); ZERO_ROW(c2); }

    // output bases for frame f0, row h0; frame f0+1 = +FRAME_STRIDE, row h0+1 = +NW
    size_t plane = (size_t)h0 * NW + w0;
    float* oL = out_lll + ((size_t)(bc * NF + f0)) * FRAME_STRIDE + plane;
    float* oD = out_det + ((size_t)(bc * 7 * NF + f0)) * FRAME_STRIDE + plane;

    // One output row: (ALO,AHI)=lower frame rows h,h+1 ; (BLO,BHI)=upper frame rows
    #define DO_ROW(ALO, AHI, BLO, BHI, OLP, ODP, ROWOFF) do {                    \
        float4 vLLL, vLLH, vLHL, vLHH, vHLL, vHLH, vHHL, vHHH;                   \
        float* rLLL=&vLLL.x; float* rLLH=&vLLH.x; float* rLHL=&vLHL.x;           \
        float* rLHH=&vLHH.x; float* rHLL=&vHLL.x; float* rHLH=&vHLH.x;           \
        float* rHHL=&vHHL.x; float* rHHH=&vHHH.x;                                \
        _Pragma("unroll")                                                        \
        for (int k = 0; k < 4; k++) {                                            \
            float wl00 = ALO[k] + ALO[k+1], wh00 = ALO[k+1] - ALO[k];            \
            float wl01 = AHI[k] + AHI[k+1], wh01 = AHI[k+1] - AHI[k];            \
            float wl10 = BLO[k] + BLO[k+1], wh10 = BLO[k+1] - BLO[k];            \
            float wl11 = BHI[k] + BHI[k+1], wh11 = BHI[k+1] - BHI[k];            \
            float q0LL = wl00 + wl01, q0LH = wh00 + wh01;                        \
            float q0HL = wl01 - wl00, q0HH = wh01 - wh00;                        \
            float q1LL = wl10 + wl11, q1LH = wh10 + wh11;                        \
            float q1HL = wl11 - wl10, q1HH = wh11 - wh10;                        \
            rLLL[k] = S3 * (q0LL + q1LL);                                        \
            rLLH[k] = S3 * (q0LH + q1LH);                                        \
            rLHL[k] = S3 * (q0HL + q1HL);                                        \
            rLHH[k] = S3 * (q0HH + q1HH);                                        \
            rHLL[k] = S3 * (q1LL - q0LL);                                        \
            rHLH[k] = S3 * (q1LH - q0LH);                                        \
            rHHL[k] = S3 * (q1HL - q0HL);                                        \
            rHHH[k] = S3 * (q1HH - q0HH);                                        \
        }                                                                        \
        __stcs((float4*)((OLP) + (ROWOFF)), vLLL);                               \
        __stcs((float4*)((ODP) + (size_t)0 * NF * FRAME_STRIDE + (ROWOFF)), vLLH);\
        __stcs((float4*)((ODP) + (size_t)1 * NF * FRAME_STRIDE + (ROWOFF)), vLHL);\
        __stcs((float4*)((ODP) + (size_t)2 * NF * FRAME_STRIDE + (ROWOFF)), vLHH);\
        __stcs((float4*)((ODP) + (size_t)3 * NF * FRAME_STRIDE + (ROWOFF)), vHLL);\
        __stcs((float4*)((ODP) + (size_t)4 * NF * FRAME_STRIDE + (ROWOFF)), vHLH);\
        __stcs((float4*)((ODP) + (size_t)5 * NF * FRAME_STRIDE + (ROWOFF)), vHHL);\
        __stcs((float4*)((ODP) + (size_t)6 * NF * FRAME_STRIDE + (ROWOFF)), vHHH);\
    } while (0)

    // output frame f0 (input frames f0, f0+1)
    DO_ROW(a0, a1, b0, b1, oL, oD, 0);
    DO_ROW(a1, a2, b1, b2, oL, oD, NW);
    // output frame f0+1 (input frames f0+1, f0+2)
    if (!flast) {   // warp-uniform
        DO_ROW(b0, b1, c0, c1, oL + FRAME_STRIDE, oD + FRAME_STRIDE, 0);
        DO_ROW(b1, b2, c1, c2, oL + FRAME_STRIDE, oD + FRAME_STRIDE, NW);
    }

    #undef DO_ROW
    #undef ZERO_ROW
    #undef LOAD_ROW
}

extern "C" void kernel_launch(void* const* d_in, const int* in_sizes, int n_in,
                              void* d_out, int out_size)
{
    const float* x = (const float*)d_in[0];
    float* out = (float*)d_out;
    float* out_lll = out;
    float* out_det = out + LLL_ELEMS;

    const int total = NBC * NFP * NHP * NW4;  // 393,216
    const int block = 128;
    const int grid = total / block;           // 3072
    haar3d_kernel<<<grid, block>>>(x, out_lll, out_det);
}